// round 1
// baseline (speedup 1.0000x reference)
#include <cuda_runtime.h>
#include <cuda_fp16.h>
#include <mma.h>
#include <math.h>

using namespace nvcuda;

// Problem dims
#define S_LEN 256
#define B_SZ  128
#define D1    1024
#define N2    2048
#define M_ROWS (S_LEN * B_SZ)   // 32768

// GEMM tiling
#define BM 128
#define BN 128
#define BK 32
#define CSM_LD 136
#define SMEM_BYTES (BM * CSM_LD * 4)   // 69632 (epilogue buffer, also covers 16KB pipeline)

// ---------------- device scratch (static; no allocations allowed) ----------------
__device__ __half g_Ah[(size_t)M_ROWS * D1];     // f1_seq in fp16            (64 MB)
__device__ __half g_Wh[(size_t)D1 * N2];         // [W11a | W12a] fp16        (4 MB)
__device__ __half g_Wbh[(size_t)N2 * N2];        // blockdiag(W11b, W12b)     (8 MB)
__device__ __half g_A2h[(size_t)B_SZ * N2];      // [f1 | f2] fp16
__device__ float  g_c[(size_t)B_SZ * N2];        // S-independent pre-activation terms
__device__ float  g_bv[N2];                      // [b11 | b12]
__device__ float  g_wv[N2];                      // [W21 | W22]
__device__ float  g_logit[2 * M_ROWS];           // s1, s2 logits
__device__ float  g_coef[M_ROWS];                // (w1+w2)*0.5/S

// ---------------- prep kernels ----------------
__global__ void zero_kernel() {
    int n = B_SZ * N2 + 2 * M_ROWS;
    for (int i = blockIdx.x * blockDim.x + threadIdx.x; i < n; i += gridDim.x * blockDim.x) {
        if (i < B_SZ * N2) g_c[i] = 0.f;
        else               g_logit[i - B_SZ * N2] = 0.f;
    }
}

__global__ void convA_kernel(const float* __restrict__ fseq) {
    // f1_seq [S,B,D1] row-major -> g_Ah same layout, fp16, vectorized
    size_t n4 = (size_t)M_ROWS * D1 / 4;
    const float4* src = (const float4*)fseq;
    __half2* dst = (__half2*)g_Ah;
    for (size_t i = blockIdx.x * (size_t)blockDim.x + threadIdx.x; i < n4;
         i += (size_t)gridDim.x * blockDim.x) {
        float4 v = src[i];
        dst[2 * i]     = __floats2half2_rn(v.x, v.y);
        dst[2 * i + 1] = __floats2half2_rn(v.z, v.w);
    }
}

__global__ void convW_kernel(const float* __restrict__ W11, const float* __restrict__ W12) {
    // g_Wh[k][n] : n<1024 -> W11[k][n] (rows 0..1023 of W11), else W12[k][n-1024]
    int n = D1 * N2;
    for (int i = blockIdx.x * blockDim.x + threadIdx.x; i < n; i += gridDim.x * blockDim.x) {
        int k = i >> 11, c = i & (N2 - 1);
        float v = (c < D1) ? W11[(size_t)k * D1 + c] : W12[(size_t)k * D1 + (c - D1)];
        g_Wh[i] = __float2half_rn(v);
    }
}

__global__ void convWb_kernel(const float* __restrict__ W11, const float* __restrict__ W12) {
    // blockdiag: [k<1024, n<1024] = W11[1024+k][n]; [k>=1024, n>=1024] = W12[k][n-1024]; else 0
    size_t n = (size_t)N2 * N2;
    for (size_t i = blockIdx.x * (size_t)blockDim.x + threadIdx.x; i < n;
         i += (size_t)gridDim.x * blockDim.x) {
        int k = (int)(i >> 11), c = (int)(i & (N2 - 1));
        float v = 0.f;
        if (k < D1 && c < D1)        v = W11[(size_t)(D1 + k) * D1 + c];
        else if (k >= D1 && c >= D1) v = W12[(size_t)k * D1 + (c - D1)];
        g_Wbh[i] = __float2half_rn(v);
    }
}

__global__ void convA2_kernel(const float* __restrict__ f1, const float* __restrict__ f2) {
    int n = B_SZ * N2;
    for (int i = blockIdx.x * blockDim.x + threadIdx.x; i < n; i += gridDim.x * blockDim.x) {
        int b = i >> 11, k = i & (N2 - 1);
        float v = (k < D1) ? f1[b * D1 + k] : f2[b * D1 + (k - D1)];
        g_A2h[i] = __float2half_rn(v);
    }
}

__global__ void convVec_kernel(const float* __restrict__ W21, const float* __restrict__ W22,
                               const float* __restrict__ b11, const float* __restrict__ b12) {
    for (int i = blockIdx.x * blockDim.x + threadIdx.x; i < N2; i += gridDim.x * blockDim.x) {
        g_wv[i] = (i < D1) ? W21[i] : W22[i - D1];
        g_bv[i] = (i < D1) ? b11[i] : b12[i - D1];
    }
}

// ---------------- GEMM (wmma) ----------------
// FUSE=true : C = Ah[32768,1024] x Wh[1024,2048], fused tanh-dot epilogue -> logits
// FUSE=false: C = A2h[128,2048] x Wbh[2048,2048], split-K over blockIdx.z -> atomic into g_c
template <bool FUSE>
__global__ void __launch_bounds__(256) gemm_kernel() {
    extern __shared__ char smem_raw[];
    __half* As = (__half*)smem_raw;        // BM x BK
    __half* Bs = As + BM * BK;             // BK x BN
    float*  Csm = (float*)smem_raw;        // BM x CSM_LD (after k-loop)

    const __half* A  = FUSE ? g_Ah : g_A2h;
    const __half* Bm = FUSE ? g_Wh : g_Wbh;
    const int lda    = FUSE ? D1 : N2;
    const int ldb    = N2;
    const int kiters = FUSE ? (D1 / BK) : 8;
    const int ktbase = FUSE ? 0 : blockIdx.z * 8;

    const int tid = threadIdx.x;
    const int m0 = blockIdx.y * BM;
    const int n0 = blockIdx.x * BN;
    const int warpId = tid >> 5;
    const int wm0 = (warpId >> 1) * 32;
    const int wn0 = (warpId & 1) * 64;

    wmma::fragment<wmma::accumulator, 16, 16, 16, float> acc[2][4];
#pragma unroll
    for (int mi = 0; mi < 2; mi++)
#pragma unroll
        for (int ni = 0; ni < 4; ni++) wmma::fill_fragment(acc[mi][ni], 0.f);

    for (int kt = 0; kt < kiters; kt++) {
        int k0 = (ktbase + kt) * BK;
#pragma unroll
        for (int t = 0; t < 2; t++) {   // A tile: 128x32 halfs = 512 x uint4
            int v = tid + t * 256;
            int r = v >> 2, c = (v & 3) * 8;
            *(uint4*)(As + r * BK + c) =
                *(const uint4*)(A + (size_t)(m0 + r) * lda + k0 + c);
        }
#pragma unroll
        for (int t = 0; t < 2; t++) {   // B tile: 32x128 halfs = 512 x uint4
            int v = tid + t * 256;
            int r = v >> 4, c = (v & 15) * 8;
            *(uint4*)(Bs + r * BN + c) =
                *(const uint4*)(Bm + (size_t)(k0 + r) * ldb + n0 + c);
        }
        __syncthreads();
#pragma unroll
        for (int kk = 0; kk < 2; kk++) {
            wmma::fragment<wmma::matrix_a, 16, 16, 16, __half, wmma::row_major> af[2];
            wmma::fragment<wmma::matrix_b, 16, 16, 16, __half, wmma::row_major> bf[4];
#pragma unroll
            for (int mi = 0; mi < 2; mi++)
                wmma::load_matrix_sync(af[mi], As + (wm0 + mi * 16) * BK + kk * 16, BK);
#pragma unroll
            for (int ni = 0; ni < 4; ni++)
                wmma::load_matrix_sync(bf[ni], Bs + (kk * 16) * BN + wn0 + ni * 16, BN);
#pragma unroll
            for (int mi = 0; mi < 2; mi++)
#pragma unroll
                for (int ni = 0; ni < 4; ni++)
                    wmma::mma_sync(acc[mi][ni], af[mi], bf[ni], acc[mi][ni]);
        }
        __syncthreads();
    }

    // spill accumulators to smem for epilogue (fragment layout is opaque)
#pragma unroll
    for (int mi = 0; mi < 2; mi++)
#pragma unroll
        for (int ni = 0; ni < 4; ni++)
            wmma::store_matrix_sync(Csm + (wm0 + mi * 16) * CSM_LD + wn0 + ni * 16,
                                    acc[mi][ni], CSM_LD, wmma::mem_row_major);
    __syncthreads();

    if (FUSE) {
        // rows of this tile are exactly b=0..127 for s=blockIdx.y
        int r = tid >> 1;           // b
        int h = tid & 1;            // half of the 128-col tile
        float sum = 0.f;
        int base = h * 64;
#pragma unroll 8
        for (int c = 0; c < 64; c++) {
            int cc = base + c;
            int n = n0 + cc;
            float x = Csm[r * CSM_LD + cc] + g_c[r * N2 + n] + g_bv[n];
            sum += tanhf(x) * g_wv[n];
        }
        sum += __shfl_xor_sync(0xffffffffu, sum, 1);
        if (h == 0)
            atomicAdd(&g_logit[(n0 >= D1 ? M_ROWS : 0) + blockIdx.y * B_SZ + r], sum);
    } else {
        for (int idx = tid; idx < BM * BN; idx += 256) {
            int r = idx >> 7, c = idx & 127;
            atomicAdd(&g_c[r * N2 + n0 + c], Csm[r * CSM_LD + c]);
        }
    }
}

// ---------------- softmax over S (per b), combine weights ----------------
__global__ void softmax_kernel() {
    int b = blockIdx.x;
    int s = threadIdx.x;   // 256 threads == S_LEN
    __shared__ float sv1[S_LEN], sv2[S_LEN];
    float v1 = g_logit[s * B_SZ + b];
    float v2 = g_logit[M_ROWS + s * B_SZ + b];
    sv1[s] = v1; sv2[s] = v2;
    __syncthreads();
    float m1 = -1e30f, m2 = -1e30f;
    for (int i = 0; i < S_LEN; i++) { m1 = fmaxf(m1, sv1[i]); m2 = fmaxf(m2, sv2[i]); }
    float z1 = 0.f, z2 = 0.f;
    for (int i = 0; i < S_LEN; i++) { z1 += expf(sv1[i] - m1); z2 += expf(sv2[i] - m2); }
    float w = (expf(v1 - m1) / z1 + expf(v2 - m2) / z2) * 0.5f / (float)S_LEN;
    g_coef[s * B_SZ + b] = w;
}

// ---------------- weighted sum over S: out[b,d] = sum_s coef[s,b]*fseq[s,b,d] ----------------
__global__ void wsum_kernel(const float* __restrict__ fseq, float* __restrict__ out) {
    int b = blockIdx.y;
    int d = blockIdx.x * 256 + threadIdx.x;
    __shared__ float as[S_LEN];
    for (int i = threadIdx.x; i < S_LEN; i += 256) as[i] = g_coef[i * B_SZ + b];
    __syncthreads();
    const float* p = fseq + (size_t)b * D1 + d;
    float acc = 0.f;
#pragma unroll 4
    for (int s = 0; s < S_LEN; s++)
        acc += as[s] * p[(size_t)s * B_SZ * D1];
    out[b * D1 + d] = acc;
}

// ---------------- launch ----------------
extern "C" void kernel_launch(void* const* d_in, const int* in_sizes, int n_in,
                              void* d_out, int out_size) {
    const float* f1   = (const float*)d_in[0];
    const float* f2   = (const float*)d_in[1];
    const float* fseq = (const float*)d_in[2];
    const float* W11  = (const float*)d_in[3];
    const float* b11  = (const float*)d_in[4];
    const float* W12  = (const float*)d_in[5];
    const float* b12  = (const float*)d_in[6];
    const float* W21  = (const float*)d_in[7];
    // d_in[8] = b21 (softmax-invariant, unused)
    const float* W22  = (const float*)d_in[9];
    // d_in[10] = b22 (unused)
    float* out = (float*)d_out;

    cudaFuncSetAttribute(gemm_kernel<true>,  cudaFuncAttributeMaxDynamicSharedMemorySize, SMEM_BYTES);
    cudaFuncSetAttribute(gemm_kernel<false>, cudaFuncAttributeMaxDynamicSharedMemorySize, SMEM_BYTES);

    zero_kernel<<<320, 256>>>();
    convA_kernel<<<4096, 256>>>(fseq);
    convW_kernel<<<2048, 256>>>(W11, W12);
    convWb_kernel<<<4096, 256>>>(W11, W12);
    convA2_kernel<<<256, 256>>>(f1, f2);
    convVec_kernel<<<8, 256>>>(W21, W22, b11, b12);

    // S-independent terms: c[b, 0:2048] = [f1@W11b | f2@W12b]  (split-K over z)
    gemm_kernel<false><<<dim3(16, 1, 8), 256, SMEM_BYTES>>>();

    // main fused GEMM + tanh-dot epilogue -> logits
    gemm_kernel<true><<<dim3(16, 256), 256, SMEM_BYTES>>>();

    softmax_kernel<<<128, 256>>>();
    wsum_kernel<<<dim3(4, 128), 256>>>(fseq, out);
}

// round 3
// speedup vs baseline: 3.3339x; 3.3339x over previous
#include <cuda_runtime.h>
#include <cuda_fp16.h>
#include <mma.h>
#include <math.h>
#include <stdint.h>

using namespace nvcuda;

// Problem dims
#define S_LEN 256
#define B_SZ  128
#define D1    1024
#define N2    2048
#define M_ROWS (S_LEN * B_SZ)   // 32768

// ---------------- device scratch (static; no allocations allowed) ----------------
__device__ __half g_Ah[(size_t)M_ROWS * D1];     // f1_seq in fp16            (64 MB)
__device__ __half g_Wt[(size_t)N2 * D1];         // [W11a|W12a]^T : [n][k]    (4 MB)
__device__ __half g_Wbh[(size_t)N2 * N2];        // blockdiag(W11b, W12b)     (8 MB)
__device__ __half g_A2h[(size_t)B_SZ * N2];      // [f1 | f2] fp16
__device__ float  g_c[(size_t)B_SZ * N2];        // S-independent pre-activation terms
__device__ float  g_bv[N2];                      // [b11 | b12]
__device__ float  g_wv[N2];                      // [W21 | W22]
__device__ float  g_logit[2 * M_ROWS];           // s1, s2 logits
__device__ float  g_coef[M_ROWS];                // (w1+w2)*0.5/S

// ---------------- PTX helpers (all sm_80-era; safe under compute_100) ----------------
__device__ __forceinline__ uint32_t smem_u32(const void* p) {
    uint32_t a;
    asm("{ .reg .u64 t; cvta.to.shared.u64 t, %1; cvt.u32.u64 %0, t; }" : "=r"(a) : "l"(p));
    return a;
}
__device__ __forceinline__ void cp16(uint32_t s, const void* g) {
    asm volatile("cp.async.cg.shared.global [%0], [%1], 16;" :: "r"(s), "l"(g));
}
__device__ __forceinline__ void cp_commit() { asm volatile("cp.async.commit_group;" ::: "memory"); }
__device__ __forceinline__ void ldsm4(uint32_t& r0, uint32_t& r1, uint32_t& r2, uint32_t& r3,
                                      uint32_t addr) {
    asm volatile("ldmatrix.sync.aligned.m8n8.x4.shared.b16 {%0,%1,%2,%3}, [%4];"
                 : "=r"(r0), "=r"(r1), "=r"(r2), "=r"(r3) : "r"(addr));
}
__device__ __forceinline__ void mma16816(float* c, uint32_t a0, uint32_t a1, uint32_t a2,
                                         uint32_t a3, uint32_t b0, uint32_t b1) {
    asm volatile(
        "mma.sync.aligned.m16n8k16.row.col.f32.f16.f16.f32 "
        "{%0,%1,%2,%3}, {%4,%5,%6,%7}, {%8,%9}, {%0,%1,%2,%3};"
        : "+f"(c[0]), "+f"(c[1]), "+f"(c[2]), "+f"(c[3])
        : "r"(a0), "r"(a1), "r"(a2), "r"(a3), "r"(b0), "r"(b1));
}
__device__ __forceinline__ float tanh_fast(float x) {
    float t;
    asm("tanh.approx.f32 %0, %1;" : "=f"(t) : "f"(x));
    return t;
}

// ---------------- prep kernels ----------------
__global__ void zero_kernel() {
    int n = B_SZ * N2 + 2 * M_ROWS;
    for (int i = blockIdx.x * blockDim.x + threadIdx.x; i < n; i += gridDim.x * blockDim.x) {
        if (i < B_SZ * N2) g_c[i] = 0.f;
        else               g_logit[i - B_SZ * N2] = 0.f;
    }
}

__global__ void convA_kernel(const float* __restrict__ fseq) {
    size_t n4 = (size_t)M_ROWS * D1 / 4;
    const float4* src = (const float4*)fseq;
    __half2* dst = (__half2*)g_Ah;
    for (size_t i = blockIdx.x * (size_t)blockDim.x + threadIdx.x; i < n4;
         i += (size_t)gridDim.x * blockDim.x) {
        float4 v = src[i];
        dst[2 * i]     = __floats2half2_rn(v.x, v.y);
        dst[2 * i + 1] = __floats2half2_rn(v.z, v.w);
    }
}

__global__ void convWt_kernel(const float* __restrict__ W11, const float* __restrict__ W12) {
    // g_Wt[n][k] = (n<1024) ? W11[k][n] : W12[k][n-1024]   (rows k=0..1023)
    int n = N2 * D1;
    for (int i = blockIdx.x * blockDim.x + threadIdx.x; i < n; i += gridDim.x * blockDim.x) {
        int r = i >> 10, k = i & (D1 - 1);
        float v = (r < D1) ? W11[(size_t)k * D1 + r] : W12[(size_t)k * D1 + (r - D1)];
        g_Wt[i] = __float2half_rn(v);
    }
}

__global__ void convWb_kernel(const float* __restrict__ W11, const float* __restrict__ W12) {
    size_t n = (size_t)N2 * N2;
    for (size_t i = blockIdx.x * (size_t)blockDim.x + threadIdx.x; i < n;
         i += (size_t)gridDim.x * blockDim.x) {
        int k = (int)(i >> 11), c = (int)(i & (N2 - 1));
        float v = 0.f;
        if (k < D1 && c < D1)        v = W11[(size_t)(D1 + k) * D1 + c];
        else if (k >= D1 && c >= D1) v = W12[(size_t)k * D1 + (c - D1)];
        g_Wbh[i] = __float2half_rn(v);
    }
}

__global__ void convA2_kernel(const float* __restrict__ f1, const float* __restrict__ f2) {
    int n = B_SZ * N2;
    for (int i = blockIdx.x * blockDim.x + threadIdx.x; i < n; i += gridDim.x * blockDim.x) {
        int b = i >> 11, k = i & (N2 - 1);
        float v = (k < D1) ? f1[b * D1 + k] : f2[b * D1 + (k - D1)];
        g_A2h[i] = __float2half_rn(v);
    }
}

__global__ void convVec_kernel(const float* __restrict__ W21, const float* __restrict__ W22,
                               const float* __restrict__ b11, const float* __restrict__ b12) {
    for (int i = blockIdx.x * blockDim.x + threadIdx.x; i < N2; i += gridDim.x * blockDim.x) {
        g_wv[i] = (i < D1) ? W21[i] : W22[i - D1];
        g_bv[i] = (i < D1) ? b11[i] : b12[i - D1];
    }
}

// ---------------- small GEMM (wmma): c[b,n] = [f1|f2] @ blockdiag, split-K ----------------
#define BMs 128
#define BNs 128
#define BKs 32
#define CSM_LD 136
#define SMEM_BYTES_S (BMs * CSM_LD * 4)

__global__ void __launch_bounds__(256) small_gemm_kernel() {
    extern __shared__ char smem_raw[];
    __half* As = (__half*)smem_raw;
    __half* Bs = As + BMs * BKs;
    float*  Csm = (float*)smem_raw;

    const int tid = threadIdx.x;
    const int n0 = blockIdx.x * BNs;
    const int warpId = tid >> 5;
    const int wm0 = (warpId >> 1) * 32;
    const int wn0 = (warpId & 1) * 64;
    const int ktbase = blockIdx.z * 8;

    wmma::fragment<wmma::accumulator, 16, 16, 16, float> acc[2][4];
#pragma unroll
    for (int mi = 0; mi < 2; mi++)
#pragma unroll
        for (int ni = 0; ni < 4; ni++) wmma::fill_fragment(acc[mi][ni], 0.f);

    for (int kt = 0; kt < 8; kt++) {
        int k0 = (ktbase + kt) * BKs;
#pragma unroll
        for (int t = 0; t < 2; t++) {
            int v = tid + t * 256;
            int r = v >> 2, c = (v & 3) * 8;
            *(uint4*)(As + r * BKs + c) = *(const uint4*)(g_A2h + (size_t)r * N2 + k0 + c);
        }
#pragma unroll
        for (int t = 0; t < 2; t++) {
            int v = tid + t * 256;
            int r = v >> 4, c = (v & 15) * 8;
            *(uint4*)(Bs + r * BNs + c) = *(const uint4*)(g_Wbh + (size_t)(k0 + r) * N2 + n0 + c);
        }
        __syncthreads();
#pragma unroll
        for (int kk = 0; kk < 2; kk++) {
            wmma::fragment<wmma::matrix_a, 16, 16, 16, __half, wmma::row_major> af[2];
            wmma::fragment<wmma::matrix_b, 16, 16, 16, __half, wmma::row_major> bf[4];
#pragma unroll
            for (int mi = 0; mi < 2; mi++)
                wmma::load_matrix_sync(af[mi], As + (wm0 + mi * 16) * BKs + kk * 16, BKs);
#pragma unroll
            for (int ni = 0; ni < 4; ni++)
                wmma::load_matrix_sync(bf[ni], Bs + (kk * 16) * BNs + wn0 + ni * 16, BNs);
#pragma unroll
            for (int mi = 0; mi < 2; mi++)
#pragma unroll
                for (int ni = 0; ni < 4; ni++)
                    wmma::mma_sync(acc[mi][ni], af[mi], bf[ni], acc[mi][ni]);
        }
        __syncthreads();
    }
#pragma unroll
    for (int mi = 0; mi < 2; mi++)
#pragma unroll
        for (int ni = 0; ni < 4; ni++)
            wmma::store_matrix_sync(Csm + (wm0 + mi * 16) * CSM_LD + wn0 + ni * 16,
                                    acc[mi][ni], CSM_LD, wmma::mem_row_major);
    __syncthreads();
    for (int idx = tid; idx < BMs * BNs; idx += 256) {
        int r = idx >> 7, c = idx & 127;
        atomicAdd(&g_c[r * N2 + n0 + c], Csm[r * CSM_LD + c]);
    }
}

// ---------------- main GEMM: mma.sync + cp.async double buffer, register epilogue ------
// C = g_Ah[32768,1024] @ g_Wt^T  -> logits.  Tile 128x128, BK=64.
#define KCHUNK 64
#define NCHUNKS 16                         // 1024 / 64
#define LDS_PAD 72                         // halfs per row (64 + 8)
#define A_SZ (128 * LDS_PAD * 2)           // 18432 B
#define STAGE_BYTES (2 * A_SZ)             // A + B = 36864 B
#define SMEM_BYTES_MAIN (2 * STAGE_BYTES)  // 73728 B

__device__ __forceinline__ void load_chunk(uint32_t sbase, int st, int kt, int m0, int n0,
                                           int tid) {
    uint32_t abase = sbase + st * STAGE_BYTES;
    uint32_t bbase = abase + A_SZ;
    const __half* Ag = g_Ah + (size_t)m0 * D1 + kt * KCHUNK;
    const __half* Bg = g_Wt + (size_t)n0 * D1 + kt * KCHUNK;
#pragma unroll
    for (int j = 0; j < 4; j++) {          // A: 128 rows x 8 x 16B
        int idx = tid + j * 256;
        int r = idx >> 3, cc = idx & 7;
        cp16(abase + (r * LDS_PAD + cc * 8) * 2, Ag + (size_t)r * D1 + cc * 8);
    }
#pragma unroll
    for (int j = 0; j < 4; j++) {          // B: 128 rows x 8 x 16B
        int idx = tid + j * 256;
        int r = idx >> 3, cc = idx & 7;
        cp16(bbase + (r * LDS_PAD + cc * 8) * 2, Bg + (size_t)r * D1 + cc * 8);
    }
    cp_commit();
}

__global__ void __launch_bounds__(256, 2) main_gemm_kernel() {
    extern __shared__ char smem[];
    uint32_t sbase = smem_u32(smem);
    const int tid = threadIdx.x;
    const int lane = tid & 31;
    const int wid = tid >> 5;
    const int mw = (wid & 3) * 32;         // warp M offset (4 warps down)
    const int nw = (wid >> 2) * 64;        // warp N offset (2 warps across)
    const int m0 = blockIdx.y * 128;       // s tile: rows are b = 0..127
    const int n0 = blockIdx.x * 128;

    // per-thread ldmatrix offsets (halfs, within stage)
    const uint32_t a_off = (uint32_t)(mw + (lane & 15)) * LDS_PAD + (lane >> 4) * 8;
    const uint32_t b_off = (uint32_t)(nw + (lane & 7) + ((lane >> 4) & 1) * 8) * LDS_PAD +
                           ((lane >> 3) & 1) * 8;

    float acc[2][8][4];
#pragma unroll
    for (int mi = 0; mi < 2; mi++)
#pragma unroll
        for (int ni = 0; ni < 8; ni++)
#pragma unroll
            for (int q = 0; q < 4; q++) acc[mi][ni][q] = 0.f;

    load_chunk(sbase, 0, 0, m0, n0, tid);
    load_chunk(sbase, 1, 1, m0, n0, tid);

    for (int kt = 0; kt < NCHUNKS; kt++) {
        int st = kt & 1;
        if (kt < NCHUNKS - 1) asm volatile("cp.async.wait_group 1;" ::: "memory");
        else                  asm volatile("cp.async.wait_group 0;" ::: "memory");
        __syncthreads();

        uint32_t sA = sbase + st * STAGE_BYTES;
        uint32_t sB = sA + A_SZ;
#pragma unroll
        for (int ks = 0; ks < 4; ks++) {
            uint32_t a[2][4];
#pragma unroll
            for (int mi = 0; mi < 2; mi++)
                ldsm4(a[mi][0], a[mi][1], a[mi][2], a[mi][3],
                      sA + (a_off + mi * 16 * LDS_PAD + ks * 16) * 2);
            uint32_t b[4][4];
#pragma unroll
            for (int p = 0; p < 4; p++)
                ldsm4(b[p][0], b[p][1], b[p][2], b[p][3],
                      sB + (b_off + p * 16 * LDS_PAD + ks * 16) * 2);
#pragma unroll
            for (int mi = 0; mi < 2; mi++)
#pragma unroll
                for (int ni = 0; ni < 8; ni++) {
                    int p = ni >> 1, h = (ni & 1) * 2;
                    mma16816(acc[mi][ni], a[mi][0], a[mi][1], a[mi][2], a[mi][3],
                             b[p][h], b[p][h + 1]);
                }
        }
        __syncthreads();
        if (kt + 2 < NCHUNKS) load_chunk(sbase, st, kt + 2, m0, n0, tid);
    }

    // ---- register epilogue: tanh(x + c + b) . wv, reduced over N ----
    const int gid = lane >> 2, tig = lane & 3;
    float rs[2][2] = {{0.f, 0.f}, {0.f, 0.f}};
#pragma unroll
    for (int ni = 0; ni < 8; ni++) {
        int col = n0 + nw + ni * 8 + 2 * tig;
        float2 bv2 = *(const float2*)(g_bv + col);
        float2 wv2 = *(const float2*)(g_wv + col);
#pragma unroll
        for (int mi = 0; mi < 2; mi++) {
            int r0 = mw + mi * 16 + gid;           // b index (rows of tile)
            float2 c0 = *(const float2*)(g_c + (size_t)r0 * N2 + col);
            float2 c1 = *(const float2*)(g_c + (size_t)(r0 + 8) * N2 + col);
            const float* a = acc[mi][ni];
            rs[mi][0] += tanh_fast(a[0] + c0.x + bv2.x) * wv2.x;
            rs[mi][0] += tanh_fast(a[1] + c0.y + bv2.y) * wv2.y;
            rs[mi][1] += tanh_fast(a[2] + c1.x + bv2.x) * wv2.x;
            rs[mi][1] += tanh_fast(a[3] + c1.y + bv2.y) * wv2.y;
        }
    }
    int sel = (n0 >= D1) ? M_ROWS : 0;
#pragma unroll
    for (int mi = 0; mi < 2; mi++)
#pragma unroll
        for (int h = 0; h < 2; h++) {
            float v = rs[mi][h];
            v += __shfl_xor_sync(0xffffffffu, v, 1);
            v += __shfl_xor_sync(0xffffffffu, v, 2);
            if (tig == 0) {
                int b = mw + mi * 16 + gid + h * 8;
                atomicAdd(&g_logit[sel + blockIdx.y * B_SZ + b], v);
            }
        }
}

// ---------------- softmax over S (per b), combine weights ----------------
__global__ void softmax_kernel() {
    int b = blockIdx.x;
    int s = threadIdx.x;   // 256 threads == S_LEN
    __shared__ float sv1[S_LEN], sv2[S_LEN];
    float v1 = g_logit[s * B_SZ + b];
    float v2 = g_logit[M_ROWS + s * B_SZ + b];
    sv1[s] = v1; sv2[s] = v2;
    __syncthreads();
    float m1 = -1e30f, m2 = -1e30f;
    for (int i = 0; i < S_LEN; i++) { m1 = fmaxf(m1, sv1[i]); m2 = fmaxf(m2, sv2[i]); }
    float z1 = 0.f, z2 = 0.f;
    for (int i = 0; i < S_LEN; i++) { z1 += expf(sv1[i] - m1); z2 += expf(sv2[i] - m2); }
    float w = (expf(v1 - m1) / z1 + expf(v2 - m2) / z2) * 0.5f / (float)S_LEN;
    g_coef[s * B_SZ + b] = w;
}

// ---------------- weighted sum over S ----------------
__global__ void wsum_kernel(const float* __restrict__ fseq, float* __restrict__ out) {
    int b = blockIdx.y;
    int d = blockIdx.x * 256 + threadIdx.x;
    __shared__ float as[S_LEN];
    for (int i = threadIdx.x; i < S_LEN; i += 256) as[i] = g_coef[i * B_SZ + b];
    __syncthreads();
    const float* p = fseq + (size_t)b * D1 + d;
    float acc = 0.f;
#pragma unroll 4
    for (int s = 0; s < S_LEN; s++)
        acc += as[s] * p[(size_t)s * B_SZ * D1];
    out[b * D1 + d] = acc;
}

// ---------------- launch ----------------
extern "C" void kernel_launch(void* const* d_in, const int* in_sizes, int n_in,
                              void* d_out, int out_size) {
    const float* f1   = (const float*)d_in[0];
    const float* f2   = (const float*)d_in[1];
    const float* fseq = (const float*)d_in[2];
    const float* W11  = (const float*)d_in[3];
    const float* b11  = (const float*)d_in[4];
    const float* W12  = (const float*)d_in[5];
    const float* b12  = (const float*)d_in[6];
    const float* W21  = (const float*)d_in[7];
    const float* W22  = (const float*)d_in[9];
    float* out = (float*)d_out;

    cudaFuncSetAttribute(small_gemm_kernel, cudaFuncAttributeMaxDynamicSharedMemorySize, SMEM_BYTES_S);
    cudaFuncSetAttribute(main_gemm_kernel,  cudaFuncAttributeMaxDynamicSharedMemorySize, SMEM_BYTES_MAIN);

    zero_kernel<<<320, 256>>>();
    convA_kernel<<<4096, 256>>>(fseq);
    convWt_kernel<<<2048, 256>>>(W11, W12);
    convWb_kernel<<<4096, 256>>>(W11, W12);
    convA2_kernel<<<256, 256>>>(f1, f2);
    convVec_kernel<<<8, 256>>>(W21, W22, b11, b12);

    // S-independent terms: c[b, 0:2048] = [f1@W11b | f2@W12b]  (split-K over z)
    small_gemm_kernel<<<dim3(16, 1, 8), 256, SMEM_BYTES_S>>>();

    // main fused GEMM (mma.sync) + tanh-dot register epilogue -> logits
    main_gemm_kernel<<<dim3(16, 256), 256, SMEM_BYTES_MAIN>>>();

    softmax_kernel<<<128, 256>>>();
    wsum_kernel<<<dim3(4, 128), 256>>>(fseq, out);
}

// round 5
// speedup vs baseline: 3.5555x; 1.0665x over previous
#include <cuda_runtime.h>
#include <cuda_fp16.h>
#include <mma.h>
#include <math.h>
#include <stdint.h>

using namespace nvcuda;

// Problem dims
#define S_LEN 256
#define B_SZ  128
#define D1    1024
#define N2    2048
#define M_ROWS (S_LEN * B_SZ)   // 32768

// ---------------- device scratch (static; no allocations allowed) ----------------
__device__ __half g_Ah[(size_t)M_ROWS * D1];     // f1_seq in fp16            (64 MB)
__device__ __half g_Wt[(size_t)N2 * D1];         // [W11a|W12a]^T : [n][k]    (4 MB)
__device__ __half g_Wbh[(size_t)N2 * N2];        // blockdiag(W11b, W12b)     (8 MB)
__device__ __half g_A2h[(size_t)B_SZ * N2];      // [f1 | f2] fp16
__device__ float  g_c[(size_t)B_SZ * N2];        // bias + S-independent pre-activation
__device__ float  g_wv[N2];                      // [W21 | W22]
__device__ float  g_logit[2 * M_ROWS];           // s1, s2 logits
__device__ float  g_coef[M_ROWS];                // (w1+w2)*0.5/S

// ---------------- PTX helpers (all sm_80-era; safe under compute_100) ----------------
__device__ __forceinline__ uint32_t smem_u32(const void* p) {
    uint32_t a;
    asm("{ .reg .u64 t; cvta.to.shared.u64 t, %1; cvt.u32.u64 %0, t; }" : "=r"(a) : "l"(p));
    return a;
}
__device__ __forceinline__ void cp16(uint32_t s, const void* g) {
    asm volatile("cp.async.cg.shared.global [%0], [%1], 16;" :: "r"(s), "l"(g));
}
__device__ __forceinline__ void cp_commit() { asm volatile("cp.async.commit_group;" ::: "memory"); }
__device__ __forceinline__ void ldsm4(uint32_t& r0, uint32_t& r1, uint32_t& r2, uint32_t& r3,
                                      uint32_t addr) {
    asm volatile("ldmatrix.sync.aligned.m8n8.x4.shared.b16 {%0,%1,%2,%3}, [%4];"
                 : "=r"(r0), "=r"(r1), "=r"(r2), "=r"(r3) : "r"(addr));
}
__device__ __forceinline__ void mma16816(float* c, uint32_t a0, uint32_t a1, uint32_t a2,
                                         uint32_t a3, uint32_t b0, uint32_t b1) {
    asm volatile(
        "mma.sync.aligned.m16n8k16.row.col.f32.f16.f16.f32 "
        "{%0,%1,%2,%3}, {%4,%5,%6,%7}, {%8,%9}, {%0,%1,%2,%3};"
        : "+f"(c[0]), "+f"(c[1]), "+f"(c[2]), "+f"(c[3])
        : "r"(a0), "r"(a1), "r"(a2), "r"(a3), "r"(b0), "r"(b1));
}
__device__ __forceinline__ float tanh_fast(float x) {
    float t;
    asm("tanh.approx.f32 %0, %1;" : "=f"(t) : "f"(x));
    return t;
}

// ---------------- prep kernels ----------------
// One merged kernel: g_c = bias, g_A2h = [f1|f2], g_logit = 0, g_wv = [W21|W22]
__global__ void prep_kernel(const float* __restrict__ f1, const float* __restrict__ f2,
                            const float* __restrict__ b11, const float* __restrict__ b12,
                            const float* __restrict__ W21, const float* __restrict__ W22) {
    int stride = gridDim.x * blockDim.x;
    int gid = blockIdx.x * blockDim.x + threadIdx.x;
    for (int i = gid; i < B_SZ * N2; i += stride) {
        int b = i >> 11, k = i & (N2 - 1);
        float bias, v;
        if (k < D1) { bias = b11[k]; v = f1[b * D1 + k]; }
        else        { bias = b12[k - D1]; v = f2[b * D1 + (k - D1)]; }
        g_c[i] = bias;
        g_A2h[i] = __float2half_rn(v);
    }
    for (int i = gid; i < 2 * M_ROWS; i += stride) g_logit[i] = 0.f;
    for (int i = gid; i < N2; i += stride)
        g_wv[i] = (i < D1) ? W21[i] : W22[i - D1];
}

__global__ void convA_kernel(const float* __restrict__ fseq) {
    size_t n4 = (size_t)M_ROWS * D1 / 4;
    const float4* src = (const float4*)fseq;
    __half2* dst = (__half2*)g_Ah;
    for (size_t i = blockIdx.x * (size_t)blockDim.x + threadIdx.x; i < n4;
         i += (size_t)gridDim.x * blockDim.x) {
        float4 v = src[i];
        dst[2 * i]     = __floats2half2_rn(v.x, v.y);
        dst[2 * i + 1] = __floats2half2_rn(v.z, v.w);
    }
}

__global__ void convWt_kernel(const float* __restrict__ W11, const float* __restrict__ W12) {
    // g_Wt[n][k] = (n<1024) ? W11[k][n] : W12[k][n-1024]   (rows k=0..1023)
    int n = N2 * D1;
    for (int i = blockIdx.x * blockDim.x + threadIdx.x; i < n; i += gridDim.x * blockDim.x) {
        int r = i >> 10, k = i & (D1 - 1);
        float v = (r < D1) ? W11[(size_t)k * D1 + r] : W12[(size_t)k * D1 + (r - D1)];
        g_Wt[i] = __float2half_rn(v);
    }
}

__global__ void convWb_kernel(const float* __restrict__ W11, const float* __restrict__ W12) {
    size_t n = (size_t)N2 * N2;
    for (size_t i = blockIdx.x * (size_t)blockDim.x + threadIdx.x; i < n;
         i += (size_t)gridDim.x * blockDim.x) {
        int k = (int)(i >> 11), c = (int)(i & (N2 - 1));
        float v = 0.f;
        if (k < D1 && c < D1)        v = W11[(size_t)(D1 + k) * D1 + c];
        else if (k >= D1 && c >= D1) v = W12[(size_t)k * D1 + (c - D1)];
        g_Wbh[i] = __float2half_rn(v);
    }
}

// ---------------- small GEMM (wmma): c[b,n] += [f1|f2] @ blockdiag, split-K ----------------
#define BMs 128
#define BNs 128
#define BKs 32
#define CSM_LD 136
#define SMEM_BYTES_S (BMs * CSM_LD * 4)

__global__ void __launch_bounds__(256) small_gemm_kernel() {
    extern __shared__ char smem_raw[];
    __half* As = (__half*)smem_raw;
    __half* Bs = As + BMs * BKs;
    float*  Csm = (float*)smem_raw;

    const int tid = threadIdx.x;
    const int n0 = blockIdx.x * BNs;
    const int warpId = tid >> 5;
    const int wm0 = (warpId >> 1) * 32;
    const int wn0 = (warpId & 1) * 64;
    const int ktbase = blockIdx.z * 8;

    wmma::fragment<wmma::accumulator, 16, 16, 16, float> acc[2][4];
#pragma unroll
    for (int mi = 0; mi < 2; mi++)
#pragma unroll
        for (int ni = 0; ni < 4; ni++) wmma::fill_fragment(acc[mi][ni], 0.f);

    for (int kt = 0; kt < 8; kt++) {
        int k0 = (ktbase + kt) * BKs;
#pragma unroll
        for (int t = 0; t < 2; t++) {
            int v = tid + t * 256;
            int r = v >> 2, c = (v & 3) * 8;
            *(uint4*)(As + r * BKs + c) = *(const uint4*)(g_A2h + (size_t)r * N2 + k0 + c);
        }
#pragma unroll
        for (int t = 0; t < 2; t++) {
            int v = tid + t * 256;
            int r = v >> 4, c = (v & 15) * 8;
            *(uint4*)(Bs + r * BNs + c) = *(const uint4*)(g_Wbh + (size_t)(k0 + r) * N2 + n0 + c);
        }
        __syncthreads();
#pragma unroll
        for (int kk = 0; kk < 2; kk++) {
            wmma::fragment<wmma::matrix_a, 16, 16, 16, __half, wmma::row_major> af[2];
            wmma::fragment<wmma::matrix_b, 16, 16, 16, __half, wmma::row_major> bf[4];
#pragma unroll
            for (int mi = 0; mi < 2; mi++)
                wmma::load_matrix_sync(af[mi], As + (wm0 + mi * 16) * BKs + kk * 16, BKs);
#pragma unroll
            for (int ni = 0; ni < 4; ni++)
                wmma::load_matrix_sync(bf[ni], Bs + (kk * 16) * BNs + wn0 + ni * 16, BNs);
#pragma unroll
            for (int mi = 0; mi < 2; mi++)
#pragma unroll
                for (int ni = 0; ni < 4; ni++)
                    wmma::mma_sync(acc[mi][ni], af[mi], bf[ni], acc[mi][ni]);
        }
        __syncthreads();
    }
#pragma unroll
    for (int mi = 0; mi < 2; mi++)
#pragma unroll
        for (int ni = 0; ni < 4; ni++)
            wmma::store_matrix_sync(Csm + (wm0 + mi * 16) * CSM_LD + wn0 + ni * 16,
                                    acc[mi][ni], CSM_LD, wmma::mem_row_major);
    __syncthreads();
    for (int idx = tid; idx < BMs * BNs; idx += 256) {
        int r = idx >> 7, c = idx & 127;
        atomicAdd(&g_c[r * N2 + n0 + c], Csm[r * CSM_LD + c]);
    }
}

// ---------------- main GEMM: mma.sync, 3-stage cp.async, register epilogue ----------
// C = g_Ah[32768,1024] @ g_Wt^T  -> logits.  Tile 128x128, BK=64, prefetch distance 2.
#define KCHUNK 64
#define NCHUNKS 16                         // 1024 / 64
#define NSTAGE 3
#define LDS_PAD 72                         // halfs per row (64 + 8)
#define A_SZ (128 * LDS_PAD * 2)           // 18432 B
#define STAGE_BYTES (2 * A_SZ)             // A + B = 36864 B
#define SMEM_BYTES_MAIN (NSTAGE * STAGE_BYTES)  // 110592 B

__device__ __forceinline__ void load_chunk(uint32_t sbase, int st, int kt, int m0, int n0,
                                           int tid) {
    uint32_t abase = sbase + st * STAGE_BYTES;
    uint32_t bbase = abase + A_SZ;
    const __half* Ag = g_Ah + (size_t)m0 * D1 + kt * KCHUNK;
    const __half* Bg = g_Wt + (size_t)n0 * D1 + kt * KCHUNK;
#pragma unroll
    for (int j = 0; j < 4; j++) {          // A: 128 rows x 8 x 16B
        int idx = tid + j * 256;
        int r = idx >> 3, cc = idx & 7;
        cp16(abase + (r * LDS_PAD + cc * 8) * 2, Ag + (size_t)r * D1 + cc * 8);
    }
#pragma unroll
    for (int j = 0; j < 4; j++) {          // B: 128 rows x 8 x 16B
        int idx = tid + j * 256;
        int r = idx >> 3, cc = idx & 7;
        cp16(bbase + (r * LDS_PAD + cc * 8) * 2, Bg + (size_t)r * D1 + cc * 8);
    }
    cp_commit();
}

__global__ void __launch_bounds__(256, 2) main_gemm_kernel() {
    extern __shared__ char smem[];
    uint32_t sbase = smem_u32(smem);
    const int tid = threadIdx.x;
    const int lane = tid & 31;
    const int wid = tid >> 5;
    const int mw = (wid & 3) * 32;         // warp M offset (4 warps down)
    const int nw = (wid >> 2) * 64;        // warp N offset (2 warps across)
    const int m0 = blockIdx.y * 128;       // s tile: rows are b = 0..127
    const int n0 = blockIdx.x * 128;

    // per-thread ldmatrix offsets (halfs, within stage)
    const uint32_t a_off = (uint32_t)(mw + (lane & 15)) * LDS_PAD + (lane >> 4) * 8;
    const uint32_t b_off = (uint32_t)(nw + (lane & 7) + ((lane >> 4) & 1) * 8) * LDS_PAD +
                           ((lane >> 3) & 1) * 8;

    float acc[2][8][4];
#pragma unroll
    for (int mi = 0; mi < 2; mi++)
#pragma unroll
        for (int ni = 0; ni < 8; ni++)
#pragma unroll
            for (int q = 0; q < 4; q++) acc[mi][ni][q] = 0.f;

    load_chunk(sbase, 0, 0, m0, n0, tid);
    load_chunk(sbase, 1, 1, m0, n0, tid);

    for (int kt = 0; kt < NCHUNKS; kt++) {
        if (kt < NCHUNKS - 1) asm volatile("cp.async.wait_group 1;" ::: "memory");
        else                  asm volatile("cp.async.wait_group 0;" ::: "memory");
        __syncthreads();
        // leading issue: prefetch chunk kt+2 into the stage freed by chunk kt-1
        if (kt + 2 < NCHUNKS) load_chunk(sbase, (kt + 2) % NSTAGE, kt + 2, m0, n0, tid);

        uint32_t sA = sbase + (kt % NSTAGE) * STAGE_BYTES;
        uint32_t sB = sA + A_SZ;
#pragma unroll
        for (int ks = 0; ks < 4; ks++) {
            uint32_t a[2][4];
#pragma unroll
            for (int mi = 0; mi < 2; mi++)
                ldsm4(a[mi][0], a[mi][1], a[mi][2], a[mi][3],
                      sA + (a_off + mi * 16 * LDS_PAD + ks * 16) * 2);
            uint32_t b[4][4];
#pragma unroll
            for (int p = 0; p < 4; p++)
                ldsm4(b[p][0], b[p][1], b[p][2], b[p][3],
                      sB + (b_off + p * 16 * LDS_PAD + ks * 16) * 2);
#pragma unroll
            for (int mi = 0; mi < 2; mi++)
#pragma unroll
                for (int ni = 0; ni < 8; ni++) {
                    int p = ni >> 1, h = (ni & 1) * 2;
                    mma16816(acc[mi][ni], a[mi][0], a[mi][1], a[mi][2], a[mi][3],
                             b[p][h], b[p][h + 1]);
                }
        }
    }

    // ---- register epilogue: tanh(x + c) . wv, reduced over N (bias folded into g_c) ----
    const int gid = lane >> 2, tig = lane & 3;
    float rs[2][2] = {{0.f, 0.f}, {0.f, 0.f}};
#pragma unroll
    for (int ni = 0; ni < 8; ni++) {
        int col = n0 + nw + ni * 8 + 2 * tig;
        float2 wv2 = *(const float2*)(g_wv + col);
#pragma unroll
        for (int mi = 0; mi < 2; mi++) {
            int r0 = mw + mi * 16 + gid;           // b index (rows of tile)
            float2 c0 = *(const float2*)(g_c + (size_t)r0 * N2 + col);
            float2 c1 = *(const float2*)(g_c + (size_t)(r0 + 8) * N2 + col);
            const float* a = acc[mi][ni];
            rs[mi][0] += tanh_fast(a[0] + c0.x) * wv2.x;
            rs[mi][0] += tanh_fast(a[1] + c0.y) * wv2.y;
            rs[mi][1] += tanh_fast(a[2] + c1.x) * wv2.x;
            rs[mi][1] += tanh_fast(a[3] + c1.y) * wv2.y;
        }
    }
    int sel = (n0 >= D1) ? M_ROWS : 0;
#pragma unroll
    for (int mi = 0; mi < 2; mi++)
#pragma unroll
        for (int h = 0; h < 2; h++) {
            float v = rs[mi][h];
            v += __shfl_xor_sync(0xffffffffu, v, 1);
            v += __shfl_xor_sync(0xffffffffu, v, 2);
            if (tig == 0) {
                int b = mw + mi * 16 + gid + h * 8;
                atomicAdd(&g_logit[sel + blockIdx.y * B_SZ + b], v);
            }
        }
}

// ---------------- softmax over S (per b), combine weights ----------------
__global__ void softmax_kernel() {
    int b = blockIdx.x;
    int s = threadIdx.x;   // 256 threads == S_LEN
    __shared__ float sv1[S_LEN], sv2[S_LEN];
    float v1 = g_logit[s * B_SZ + b];
    float v2 = g_logit[M_ROWS + s * B_SZ + b];
    sv1[s] = v1; sv2[s] = v2;
    __syncthreads();
    float m1 = -1e30f, m2 = -1e30f;
    for (int i = 0; i < S_LEN; i++) { m1 = fmaxf(m1, sv1[i]); m2 = fmaxf(m2, sv2[i]); }
    float z1 = 0.f, z2 = 0.f;
    for (int i = 0; i < S_LEN; i++) { z1 += expf(sv1[i] - m1); z2 += expf(sv2[i] - m2); }
    float w = (expf(v1 - m1) / z1 + expf(v2 - m2) / z2) * 0.5f / (float)S_LEN;
    g_coef[s * B_SZ + b] = w;
}

// ---------------- weighted sum over S (reads fp16 g_Ah, vectorized) ----------------
__global__ void wsum_kernel(float* __restrict__ out) {
    int b = blockIdx.y;
    int d2 = blockIdx.x * 256 + threadIdx.x;   // half2 index: 512 per b
    __shared__ float as[S_LEN];
    for (int i = threadIdx.x; i < S_LEN; i += 256) as[i] = g_coef[i * B_SZ + b];
    __syncthreads();
    const __half2* p = (const __half2*)g_Ah + (size_t)b * (D1 / 2) + d2;
    float ax = 0.f, ay = 0.f;
#pragma unroll 4
    for (int s = 0; s < S_LEN; s++) {
        float2 v = __half22float2(p[(size_t)s * B_SZ * (D1 / 2)]);
        float w = as[s];
        ax += w * v.x; ay += w * v.y;
    }
    float2 r; r.x = ax; r.y = ay;
    *(float2*)(out + (size_t)b * D1 + d2 * 2) = r;
}

// ---------------- launch ----------------
extern "C" void kernel_launch(void* const* d_in, const int* in_sizes, int n_in,
                              void* d_out, int out_size) {
    const float* f1   = (const float*)d_in[0];
    const float* f2   = (const float*)d_in[1];
    const float* fseq = (const float*)d_in[2];
    const float* W11  = (const float*)d_in[3];
    const float* b11  = (const float*)d_in[4];
    const float* W12  = (const float*)d_in[5];
    const float* b12  = (const float*)d_in[6];
    const float* W21  = (const float*)d_in[7];
    const float* W22  = (const float*)d_in[9];
    float* out = (float*)d_out;

    cudaFuncSetAttribute(small_gemm_kernel, cudaFuncAttributeMaxDynamicSharedMemorySize, SMEM_BYTES_S);
    cudaFuncSetAttribute(main_gemm_kernel,  cudaFuncAttributeMaxDynamicSharedMemorySize, SMEM_BYTES_MAIN);

    prep_kernel<<<512, 256>>>(f1, f2, b11, b12, W21, W22);
    convA_kernel<<<4096, 256>>>(fseq);
    convWt_kernel<<<2048, 256>>>(W11, W12);
    convWb_kernel<<<4096, 256>>>(W11, W12);

    // S-independent terms: c[b, 0:2048] += [f1@W11b | f2@W12b]  (split-K over z)
    small_gemm_kernel<<<dim3(16, 1, 8), 256, SMEM_BYTES_S>>>();

    // main fused GEMM (mma.sync) + tanh-dot register epilogue -> logits
    main_gemm_kernel<<<dim3(16, 256), 256, SMEM_BYTES_MAIN>>>();

    softmax_kernel<<<128, 256>>>();
    wsum_kernel<<<dim3(2, 128), 256>>>(out);
}